// round 3
// baseline (speedup 1.0000x reference)
#include <cuda_runtime.h>
#include <cstddef>

#define TT 1024
#define BB 16
#define CC 64
#define BANDS 32          // bands (CTAs) per batch; 32 rows each
#define CH 8              // boundary handoff chunk (columns)
#define BIGF 1e10f
// 1/(gamma*ln2), gamma = 0.01
#define KS 144.2695040888963f
// gamma*ln2
#define GLN2 0.006931471805599453f

// Scratch (device globals: allocation-free rule)
__device__ float g_cost[(size_t)BB * TT * TT];       // 64 MB, row-major per batch
__device__ float g_nx[BB * TT];
__device__ float g_ny[BB * TT];
__device__ float g_partial[BB];
__device__ float g_bound[BB][BANDS][TT + 8];         // band boundary rows, indexed by column c (1..TT)
__device__ int   g_flag[BB][BANDS];                  // columns-completed / CH per band

__device__ __forceinline__ float ex2f(float x) {
    float y;
    asm("ex2.approx.ftz.f32 %0, %1;" : "=f"(y) : "f"(x));
    return y;
}
__device__ __forceinline__ float lg2f(float x) {
    float y;
    asm("lg2.approx.ftz.f32 %0, %1;" : "=f"(y) : "f"(x));
    return y;
}
__device__ __forceinline__ int ld_acq(const int* p) {
    int v;
    asm volatile("ld.global.acquire.gpu.b32 %0, [%1];" : "=r"(v) : "l"(p));
    return v;
}
__device__ __forceinline__ void st_rel(int* p, int v) {
    asm volatile("st.global.release.gpu.b32 [%0], %1;" :: "l"(p), "r"(v));
}
__device__ __forceinline__ void stcg(float* p, float v) {
    asm volatile("st.global.cg.f32 [%0], %1;" :: "l"(p), "f"(v));
}
__device__ __forceinline__ float ldcg(const float* p) {
    float v;
    asm volatile("ld.global.cg.f32 %0, [%1];" : "=f"(v) : "l"(p));
    return v;
}

// ---------------------------------------------------------------------------
// Kernel 0: row norms  ||x_i||^2, ||y_j||^2  (one warp per row)
// ---------------------------------------------------------------------------
__global__ void norms_kernel(const float* __restrict__ x,
                             const float* __restrict__ y) {
    int gwarp = (blockIdx.x * blockDim.x + threadIdx.x) >> 5;
    int lane = threadIdx.x & 31;
    const int nrows = BB * TT;
    if (gwarp >= 2 * nrows) return;
    const float* src = (gwarp < nrows) ? x : y;
    float* dst = (gwarp < nrows) ? g_nx : g_ny;
    int row = (gwarp < nrows) ? gwarp : (gwarp - nrows);
    float v0 = src[(size_t)row * CC + lane];
    float v1 = src[(size_t)row * CC + 32 + lane];
    float s = v0 * v0 + v1 * v1;
    #pragma unroll
    for (int o = 16; o; o >>= 1) s += __shfl_xor_sync(0xFFFFFFFFu, s, o);
    if (lane == 0) dst[row] = s;
}

// ---------------------------------------------------------------------------
// Kernel 1: cost[b][i][j] = x2[i] + y2[j] - 2 * dot(x_i, y_j)
// 128x128 tile per CTA, 8x8 cells per thread.
// ---------------------------------------------------------------------------
__global__ __launch_bounds__(256) void cost_kernel(const float* __restrict__ x,
                                                   const float* __restrict__ y) {
    __shared__ float xs[32][132];
    __shared__ float ys[32][132];

    int b = blockIdx.z;
    int I0 = blockIdx.y * 128;
    int J0 = blockIdx.x * 128;
    int tid = threadIdx.x;
    int tx = tid & 15;
    int ty = tid >> 4;

    const float* xb = x + ((size_t)b * TT + I0) * CC;
    const float* yb = y + ((size_t)b * TT + J0) * CC;

    float acc[8][8];
    #pragma unroll
    for (int r = 0; r < 8; r++)
        #pragma unroll
        for (int s = 0; s < 8; s++) acc[r][s] = 0.f;

    for (int k0 = 0; k0 < CC; k0 += 32) {
        __syncthreads();
        #pragma unroll
        for (int e = 0; e < 4096; e += 256) {
            int idx = e + tid;
            int row = idx >> 5;
            int kk = idx & 31;
            xs[kk][row] = xb[(size_t)row * CC + k0 + kk];
            ys[kk][row] = yb[(size_t)row * CC + k0 + kk];
        }
        __syncthreads();
        #pragma unroll
        for (int kk = 0; kk < 32; kk++) {
            float4 xv0 = *(const float4*)&xs[kk][ty * 8];
            float4 xv1 = *(const float4*)&xs[kk][ty * 8 + 4];
            float4 yv0 = *(const float4*)&ys[kk][tx * 8];
            float4 yv1 = *(const float4*)&ys[kk][tx * 8 + 4];
            float xr[8] = {xv0.x, xv0.y, xv0.z, xv0.w, xv1.x, xv1.y, xv1.z, xv1.w};
            float yr[8] = {yv0.x, yv0.y, yv0.z, yv0.w, yv1.x, yv1.y, yv1.z, yv1.w};
            #pragma unroll
            for (int r = 0; r < 8; r++)
                #pragma unroll
                for (int s = 0; s < 8; s++)
                    acc[r][s] = fmaf(xr[r], yr[s], acc[r][s]);
        }
    }

    float x2[8], y2[8];
    #pragma unroll
    for (int r = 0; r < 8; r++) x2[r] = g_nx[b * TT + I0 + ty * 8 + r];
    #pragma unroll
    for (int s = 0; s < 8; s++) y2[s] = g_ny[b * TT + J0 + tx * 8 + s];

    float* crow = g_cost + ((size_t)b << 20) + (size_t)(I0 + ty * 8) * TT + J0 + tx * 8;
    #pragma unroll
    for (int r = 0; r < 8; r++) {
        float4 o0, o1;
        o0.x = fmaf(-2.f, acc[r][0], x2[r] + y2[0]);
        o0.y = fmaf(-2.f, acc[r][1], x2[r] + y2[1]);
        o0.z = fmaf(-2.f, acc[r][2], x2[r] + y2[2]);
        o0.w = fmaf(-2.f, acc[r][3], x2[r] + y2[3]);
        o1.x = fmaf(-2.f, acc[r][4], x2[r] + y2[4]);
        o1.y = fmaf(-2.f, acc[r][5], x2[r] + y2[5]);
        o1.z = fmaf(-2.f, acc[r][6], x2[r] + y2[6]);
        o1.w = fmaf(-2.f, acc[r][7], x2[r] + y2[7]);
        *(float4*)&crow[(size_t)r * TT] = o0;
        *(float4*)&crow[(size_t)r * TT + 4] = o1;
    }
}

// ---------------------------------------------------------------------------
// Kernel 1b: reset band-chain flags (device globals persist across replays).
// ---------------------------------------------------------------------------
__global__ void init_flags() {
    int t = threadIdx.x;
    if (t < BB * BANDS) ((int*)g_flag)[t] = 0;
}

// ---------------------------------------------------------------------------
// Kernel 2: soft-DTW, lane-skewed warp pipeline + chained bands.
// Grid (BANDS, BB), 32 threads. Band = 32 rows. Lane l owns row base+l+1;
// at step s it computes column c = s - l. Up/diag via __shfl_up; band
// boundary handed off through g_bound + acquire/release flag per CH columns.
// ---------------------------------------------------------------------------
__global__ __launch_bounds__(32) void dp_kernel() {
    const int band = blockIdx.x;
    const int b = blockIdx.y;
    const int lane = threadIdx.x;
    const int row = band * 32 + lane + 1;          // 1..TT

    const float* crow = g_cost + ((size_t)b << 20) + (size_t)(row - 1) * TT; // index by (c-1)
    float* bout = &g_bound[b][band][0];
    const float* bin = &g_bound[b][band - 1][0];   // only used when band>0
    int* flg_out = &g_flag[b][band];
    const int* flg_in = &g_flag[b][band - 1];

    float myR = BIGF;    // this lane's R at its previous step (row, c_prev)
    float prev = BIGF;   // R[row][c-1] (left)
    float diag = (band == 0 && lane == 0) ? 0.f : BIGF;  // R[row-1][c-1]; R[0][0]=0 seed
    float bch = BIGF;    // boundary chunk value held by lanes 0..CH-1

    // cost prefetch: current group of 8 (a0,a1) + next group (p0,p1)
    float4 a0, a1;
    float4 p0 = *(const float4*)(crow + 0);
    float4 p1 = *(const float4*)(crow + 4);
    a0 = p0; a1 = p1;

    for (int s = 1; s <= TT + 31; ++s) {
        // refresh boundary chunk (band>0): columns [s, s+CH-1] for lane 0
        if (band > 0 && s <= TT && ((s - 1) & (CH - 1)) == 0) {
            int t = ((s - 1) >> 3) + 1;  // chunk index (CH==8)
            int f = ld_acq(flg_in);
            while (f < t) { __nanosleep(100); f = ld_acq(flg_in); }
            if (lane < CH) bch = ldcg(bin + (t - 1) * CH + 1 + lane);
        }
        float bval = __shfl_sync(0xFFFFFFFFu, bch, (s - 1) & (CH - 1));

        float up = __shfl_up_sync(0xFFFFFFFFu, myR, 1);   // R[row-1][c]
        if (lane == 0) up = (band == 0) ? BIGF : bval;

        int c = s - lane;
        if (c >= 1 && c <= TT) {
            int p = (c - 1) & 7;
            if (p == 0) {
                a0 = p0; a1 = p1;
                if (c + 8 <= TT) {
                    const float4* g = (const float4*)(crow + (c - 1) + 8);
                    p0 = g[0]; p1 = g[1];
                }
            }
            // 8-way select of this column's cost
            float s0 = (p & 1) ? a0.y : a0.x;
            float s1 = (p & 1) ? a0.w : a0.z;
            float s2 = (p & 1) ? a1.y : a1.x;
            float s3 = (p & 1) ? a1.w : a1.z;
            float t0 = (p & 2) ? s1 : s0;
            float t1 = (p & 2) ? s3 : s2;
            float cv = (p & 4) ? t1 : t0;

            float m = fminf(fminf(prev, up), diag);
            float mk = m * KS;
            float e = ex2f(fmaf(-KS, prev, mk))
                    + ex2f(fmaf(-KS, up,   mk))
                    + ex2f(fmaf(-KS, diag, mk));
            float r = fmaf(-GLN2, lg2f(e), cv + m);

            prev = r;
            myR = r;

            if (lane == 31) {
                if (band < BANDS - 1) {
                    stcg(bout + c, r);
                    if ((c & (CH - 1)) == 0) {
                        __threadfence();
                        st_rel(flg_out, c >> 3);
                    }
                } else if (c == TT) {
                    g_partial[b] = r;   // R[T][T]
                }
            }
        }
        diag = up;   // next column's diag = this column's up
    }
}

// ---------------------------------------------------------------------------
// Kernel 3: deterministic sum of the 16 per-batch distances.
// ---------------------------------------------------------------------------
__global__ void sum_kernel(float* out) {
    if (threadIdx.x == 0) {
        float s = 0.f;
        #pragma unroll
        for (int b = 0; b < BB; b++) s += g_partial[b];
        out[0] = s;
    }
}

extern "C" void kernel_launch(void* const* d_in, const int* in_sizes, int n_in,
                              void* d_out, int out_size) {
    const float* x = (const float*)d_in[0];
    const float* y = (const float*)d_in[1];
    float* out = (float*)d_out;

    init_flags<<<1, 512>>>();
    norms_kernel<<<4096, 256>>>(x, y);
    cost_kernel<<<dim3(8, 8, BB), 256>>>(x, y);
    dp_kernel<<<dim3(BANDS, BB), 32>>>();
    sum_kernel<<<1, 32>>>(out);
}